// round 17
// baseline (speedup 1.0000x reference)
#include <cuda_runtime.h>
#include <cstdint>

#define HID   2048
#define NH    16
#define HD    128
#define QKV_N 2304
#define BB    2
#define SS    2048
#define MTOT  4096

// Scratch (no allocs allowed)
__device__ float g_qkv[(size_t)MTOT * QKV_N];
__device__ float g_att[(size_t)MTOT * HID];

// ---------------------------------------------------------------------------
// helpers
// ---------------------------------------------------------------------------
__device__ __forceinline__ uint32_t smem_u32(const void* p) {
    uint32_t a;
    asm("{ .reg .u64 t; cvta.to.shared.u64 t, %1; cvt.u32.u64 %0, t; }" : "=r"(a) : "l"(p));
    return a;
}
__device__ __forceinline__ void cp16(uint32_t s, const void* g) {
    asm volatile("cp.async.cg.shared.global [%0], [%1], 16;" :: "r"(s), "l"(g) : "memory");
}
#define CP_COMMIT() asm volatile("cp.async.commit_group;" ::: "memory")
#define CP_WAIT1()  asm volatile("cp.async.wait_group 1;" ::: "memory")
#define CP_WAIT0()  asm volatile("cp.async.wait_group 0;" ::: "memory")

// ---------------------------------------------------------------------------
// SGEMM with bias: BM=BN=128, BK=16, 256 threads, 8x8 microtile.
// 3-stage cp.async pipeline, one __syncthreads per k-block.
// A stored [m][16] per stage (cp.async contiguous; fragment reads broadcast).
// B stored [k][128]; fragments at tx*4 and 64+tx*4 (conflict-free).
// ---------------------------------------------------------------------------
#define GSTG 16384                 // bytes per stage: A 8192 + B 8192
#define SGEMM_SMEM (3 * GSTG)      // 49152 B

__device__ __forceinline__ void gemm_issue(
    uint32_t smb, int stage, const float* __restrict__ Ab,
    const float* __restrict__ Bb, int k0, int N, int K, int tid)
{
    const uint32_t abase = smb + (uint32_t)stage * GSTG;
    const uint32_t bbase = abase + 8192;
#pragma unroll
    for (int it = 0; it < 2; it++) {
        int c = tid + it * 256;                // 0..511
        int ar = c >> 2, akc = c & 3;          // A: row, 16B k-chunk
        cp16(abase + (uint32_t)(ar * 64 + akc * 16),
             Ab + (size_t)ar * K + k0 + akc * 4);
        int bkr = c >> 5, bc = c & 31;         // B: k-row, 16B n-chunk
        cp16(bbase + (uint32_t)(bkr * 512 + bc * 16),
             Bb + (size_t)(k0 + bkr) * N + bc * 4);
    }
    CP_COMMIT();
}

__global__ __launch_bounds__(256, 2) void sgemm_bias(
    const float* __restrict__ A, const float* __restrict__ Bm,
    const float* __restrict__ bias, float* __restrict__ C,
    int M, int N, int K)
{
    extern __shared__ char sg[];
    const uint32_t smb = smem_u32(sg);

    const int bx = blockIdx.x;
    const int by = blockIdx.y;
    const int tid = threadIdx.x;
    const int tx = tid % 16;
    const int ty = tid / 16;

    const float* Ab = A + (size_t)by * 128 * K;
    const float* Bb = Bm + (size_t)bx * 128;

    float acc[8][8];
#pragma unroll
    for (int i = 0; i < 8; i++)
#pragma unroll
        for (int j = 0; j < 8; j++) acc[i][j] = 0.f;

    const int NC = K / 16;

    gemm_issue(smb, 0, Ab, Bb, 0, N, K, tid);
    gemm_issue(smb, 1, Ab, Bb, 16, N, K, tid);

    for (int c = 0; c < NC; c++) {
        if (c + 1 < NC) CP_WAIT1(); else CP_WAIT0();
        __syncthreads();            // block c visible; stage (c+2)%3 free
        if (c + 2 < NC)
            gemm_issue(smb, (c + 2) % 3, Ab, Bb, (c + 2) * 16, N, K, tid);

        const int stage = c % 3;
        const float* Asf = (const float*)(sg + (size_t)stage * GSTG);        // [128][16]
        const float* Bsf = (const float*)(sg + (size_t)stage * GSTG + 8192); // [16][128]

#pragma unroll
        for (int k4 = 0; k4 < 4; k4++) {
            float4 af[8];
#pragma unroll
            for (int i = 0; i < 8; i++)
                af[i] = *(const float4*)&Asf[(ty * 8 + i) * 16 + k4 * 4];    // broadcast
#pragma unroll
            for (int kk = 0; kk < 4; kk++) {
                const int k = k4 * 4 + kk;
                float4 b0 = *(const float4*)&Bsf[k * 128 + tx * 4];          // conflict-free
                float4 b1 = *(const float4*)&Bsf[k * 128 + 64 + tx * 4];     // conflict-free
                float bv[8] = {b0.x, b0.y, b0.z, b0.w, b1.x, b1.y, b1.z, b1.w};
#pragma unroll
                for (int i = 0; i < 8; i++) {
                    float a = (kk == 0) ? af[i].x : (kk == 1) ? af[i].y
                             : (kk == 2) ? af[i].z : af[i].w;
#pragma unroll
                    for (int j = 0; j < 8; j++)
                        acc[i][j] += a * bv[j];
                }
            }
        }
    }

    const int col = bx * 128 + tx * 4;
    float4 bi0 = *(const float4*)(bias + col);
    float4 bi1 = *(const float4*)(bias + col + 64);
#pragma unroll
    for (int i = 0; i < 8; i++) {
        int row = by * 128 + ty * 8 + i;
        float4 o0, o1;
        o0.x = acc[i][0] + bi0.x; o0.y = acc[i][1] + bi0.y;
        o0.z = acc[i][2] + bi0.z; o0.w = acc[i][3] + bi0.w;
        o1.x = acc[i][4] + bi1.x; o1.y = acc[i][5] + bi1.y;
        o1.z = acc[i][6] + bi1.z; o1.w = acc[i][7] + bi1.w;
        *(float4*)(C + (size_t)row * N + col)      = o0;
        *(float4*)(C + (size_t)row * N + col + 64) = o1;
    }
}

// ---------------------------------------------------------------------------
// MQA flash attention (causal), fp32, warp-autonomous subtiles.
// (unchanged from R15/R16 — best measured)
// ---------------------------------------------------------------------------
// smem floats: Qs 16384 | Kt 2*8192 | Vs 2*8192 | Ps 8192
#define Q_OFF   0
#define KT_OFF  16384
#define VS_OFF  (KT_OFF + 16384)
#define PS_OFF  (VS_OFF + 16384)
#define ATT_SMEM ((PS_OFF + 8192) * 4)     // 229376 B

__device__ __forceinline__ void issue_kv(
    uint32_t smb, int slot, const float* __restrict__ qkv,
    int b, int k0, int tid)
{
    const uint32_t kbase = smb + (KT_OFF + slot * 8192) * 4;
    const uint32_t vbase = smb + (VS_OFF + slot * 8192) * 4;
#pragma unroll
    for (int it = 0; it < 4; it++) {
        int c = tid + it * 512;            // 0..2047
        int kk4 = c >> 6, krow = c & 63;
        cp16(kbase + (uint32_t)(kk4 * 64 + krow) * 16,
             qkv + (size_t)(b * SS + k0 + krow) * QKV_N + HID + kk4 * 4);
        int vrow = c >> 5, vc = c & 31;
        cp16(vbase + (uint32_t)(vrow * 128 + vc * 4) * 4,
             qkv + (size_t)(b * SS + k0 + vrow) * QKV_N + HID + HD + vc * 4);
    }
    CP_COMMIT();
}

__global__ __launch_bounds__(512, 1) void mqa_kernel(
    const float* __restrict__ qkv, float* __restrict__ out)
{
    extern __shared__ float smf[];
    const uint32_t smb = smem_u32(smf);
    float* Qs = smf + Q_OFF;
    float* Ps = smf + PS_OFF;

    const int qt = (int)gridDim.x - 1 - (int)blockIdx.x;   // heavy tiles first
    const int h = blockIdx.y, b = blockIdx.z;
    const int tid = threadIdx.x;
    const int q0 = qt * 128;
    const float scale = 0.088388347648318447f;   // 1/sqrt(128)
    const int jmax = 2 * qt + 1;

    issue_kv(smb, 0, qkv, b, 0, tid);

    for (int i = tid; i < 128 * 32; i += 512) {
        int r = i >> 5, c4 = (i & 31) * 4;
        *(float4*)(Qs + r * 128 + c4) =
            *(const float4*)(qkv + (size_t)(b * SS + q0 + r) * QKV_N + h * HD + c4);
    }

    const int wid = tid >> 5, lane = tid & 31;
    const int r0 = 8 * wid;

    float m_i[8], l_i[8];
#pragma unroll
    for (int i = 0; i < 8; i++) { m_i[i] = -1e30f; l_i[i] = 0.f; }

    float acc[8][4];
#pragma unroll
    for (int i = 0; i < 8; i++)
#pragma unroll
        for (int d = 0; d < 4; d++) acc[i][d] = 0.f;

    for (int j = 0; j <= jmax; j++) {
        const int slot = j & 1;
        const int k0 = j * 64;

        CP_WAIT0();
        __syncthreads();
        if (j < jmax)
            issue_kv(smb, 1 - slot, qkv, b, k0 + 64, tid);

        // -------- phase A: scores 8x2 microtile --------
        const float4* Kt4 = (const float4*)(smf + KT_OFF + slot * 8192);
        float s[8][2];
#pragma unroll
        for (int i = 0; i < 8; i++) { s[i][0] = 0.f; s[i][1] = 0.f; }

#pragma unroll 4
        for (int k4 = 0; k4 < 32; k4++) {
            float4 kk0 = Kt4[k4 * 64 + lane];
            float4 kk1 = Kt4[k4 * 64 + lane + 32];
#pragma unroll
            for (int i = 0; i < 8; i++) {
                float4 q = *(const float4*)(Qs + (r0 + i) * 128 + 4 * k4);
                s[i][0] += q.x * kk0.x + q.y * kk0.y + q.z * kk0.z + q.w * kk0.w;
                s[i][1] += q.x * kk1.x + q.y * kk1.y + q.z * kk1.z + q.w * kk1.w;
            }
        }

        // -------- softmax (in-warp, in-reg) --------
        const bool diag = (j >= 2 * qt);
        float corr[8];
#pragma unroll
        for (int i = 0; i < 8; i++) {
            const int row = q0 + r0 + i;
            float v0 = s[i][0] * scale, v1 = s[i][1] * scale;
            if (diag) {
                if (k0 + lane      > row) v0 = -1e30f;
                if (k0 + lane + 32 > row) v1 = -1e30f;
            }
            float ml = fmaxf(v0, v1);
            ml = fmaxf(ml, __shfl_xor_sync(0xffffffffu, ml, 1));
            ml = fmaxf(ml, __shfl_xor_sync(0xffffffffu, ml, 2));
            ml = fmaxf(ml, __shfl_xor_sync(0xffffffffu, ml, 4));
            ml = fmaxf(ml, __shfl_xor_sync(0xffffffffu, ml, 8));
            ml = fmaxf(ml, __shfl_xor_sync(0xffffffffu, ml, 16));
            float mnew = fmaxf(m_i[i], ml);
            corr[i] = __expf(m_i[i] - mnew);
            float p0 = __expf(v0 - mnew);
            float p1 = __expf(v1 - mnew);
            s[i][0] = p0; s[i][1] = p1;
            float ps = p0 + p1;
            ps += __shfl_xor_sync(0xffffffffu, ps, 1);
            ps += __shfl_xor_sync(0xffffffffu, ps, 2);
            ps += __shfl_xor_sync(0xffffffffu, ps, 4);
            ps += __shfl_xor_sync(0xffffffffu, ps, 8);
            ps += __shfl_xor_sync(0xffffffffu, ps, 16);
            l_i[i] = l_i[i] * corr[i] + ps;
            m_i[i] = mnew;
        }

        // publish P to own rows (pitch 64)
#pragma unroll
        for (int i = 0; i < 8; i++) {
            Ps[(r0 + i) * 64 + lane]      = s[i][0];
            Ps[(r0 + i) * 64 + lane + 32] = s[i][1];
        }
        __syncwarp();

        // -------- phase B: acc = acc*corr + P @ V  (own rows only) --------
#pragma unroll
        for (int i = 0; i < 8; i++) {
#pragma unroll
            for (int d = 0; d < 4; d++) acc[i][d] *= corr[i];
        }
        const float* Vsf = smf + VS_OFF + slot * 8192;
#pragma unroll 2
        for (int c4 = 0; c4 < 16; c4++) {
            float4 v[4];
#pragma unroll
            for (int cc = 0; cc < 4; cc++)
                v[cc] = *(const float4*)(Vsf + (4 * c4 + cc) * 128 + 4 * lane);
#pragma unroll
            for (int hf = 0; hf < 2; hf++) {
                float4 pv[4];
#pragma unroll
                for (int i4 = 0; i4 < 4; i4++)
                    pv[i4] = *(const float4*)(Ps + (r0 + 4 * hf + i4) * 64 + 4 * c4);
#pragma unroll
                for (int i4 = 0; i4 < 4; i4++) {
                    const int i = 4 * hf + i4;
                    acc[i][0] += pv[i4].x * v[0].x; acc[i][1] += pv[i4].x * v[0].y;
                    acc[i][2] += pv[i4].x * v[0].z; acc[i][3] += pv[i4].x * v[0].w;
                    acc[i][0] += pv[i4].y * v[1].x; acc[i][1] += pv[i4].y * v[1].y;
                    acc[i][2] += pv[i4].y * v[1].z; acc[i][3] += pv[i4].y * v[1].w;
                    acc[i][0] += pv[i4].z * v[2].x; acc[i][1] += pv[i4].z * v[2].y;
                    acc[i][2] += pv[i4].z * v[2].z; acc[i][3] += pv[i4].z * v[2].w;
                    acc[i][0] += pv[i4].w * v[3].x; acc[i][1] += pv[i4].w * v[3].y;
                    acc[i][2] += pv[i4].w * v[3].z; acc[i][3] += pv[i4].w * v[3].w;
                }
            }
        }
    }

    // epilogue (all state in-warp)
#pragma unroll
    for (int i = 0; i < 8; i++) {
        float linv = 1.f / l_i[i];
        int qg = q0 + r0 + i;
        float* dst = out + (size_t)(b * SS + qg) * HID + h * HD + 4 * lane;
        *(float4*)dst = make_float4(acc[i][0] * linv, acc[i][1] * linv,
                                    acc[i][2] * linv, acc[i][3] * linv);
    }
}

// ---------------------------------------------------------------------------
// kernel_launch
// ---------------------------------------------------------------------------
extern "C" void kernel_launch(void* const* d_in, const int* in_sizes, int n_in,
                              void* d_out, int out_size)
{
    const float* hidden = (const float*)d_in[0];
    const float* w1     = (const float*)d_in[2];
    const float* b1     = (const float*)d_in[3];
    const float* w2     = (const float*)d_in[4];
    const float* b2     = (const float*)d_in[5];
    float* out          = (float*)d_out;

    float *qkv, *att;
    cudaGetSymbolAddress((void**)&qkv, g_qkv);
    cudaGetSymbolAddress((void**)&att, g_att);

    cudaFuncSetAttribute(sgemm_bias, cudaFuncAttributeMaxDynamicSharedMemorySize, SGEMM_SMEM);
    cudaFuncSetAttribute(mqa_kernel, cudaFuncAttributeMaxDynamicSharedMemorySize, ATT_SMEM);

    // QKV projection
    dim3 g1(QKV_N / 128, MTOT / 128);
    sgemm_bias<<<g1, 256, SGEMM_SMEM>>>(hidden, w1, b1, qkv, MTOT, QKV_N, HID);

    // attention
    mqa_kernel<<<dim3(SS / 128, NH, BB), 512, ATT_SMEM>>>(qkv, att);

    // output projection
    dim3 g2(HID / 128, MTOT / 128);
    sgemm_bias<<<g2, 256, SGEMM_SMEM>>>(att, w2, b2, out, MTOT, HID, HID);
}